// round 5
// baseline (speedup 1.0000x reference)
#include <cuda_runtime.h>
#include <cuda_bf16.h>
#include <cstdint>
#include <cstddef>

#define B_DIM 32
#define HDIM  512
#define NDIM  4096
#define MDIM  128
#define TDIM  256

// __device__ scratch (allocation-free rule). Wp as bf16 hi/lo, two layouts.
__device__ __align__(16) __nv_bfloat16 g_WpT_hi[B_DIM * MDIM * HDIM]; // [b][m][h]
__device__ __align__(16) __nv_bfloat16 g_WpT_lo[B_DIM * MDIM * HDIM];
__device__ __align__(16) __nv_bfloat16 g_Wp_hi [B_DIM * HDIM * MDIM]; // [b][h][m]
__device__ __align__(16) __nv_bfloat16 g_Wp_lo [B_DIM * HDIM * MDIM];

// ---------------- helpers (all non-arch-specific PTX) ----------------
__device__ __forceinline__ uint32_t smem_u32(const void* p) {
    uint32_t a;
    asm("{ .reg .u64 t; cvta.to.shared.u64 t, %1; cvt.u32.u64 %0, t; }"
        : "=r"(a) : "l"(p));
    return a;
}
__device__ __forceinline__ void ldsm4(uint32_t* r, uint32_t a) {
    asm volatile("ldmatrix.sync.aligned.m8n8.x4.shared.b16 {%0,%1,%2,%3}, [%4];"
        : "=r"(r[0]), "=r"(r[1]), "=r"(r[2]), "=r"(r[3]) : "r"(a));
}
__device__ __forceinline__ void ldsm4t(uint32_t* r, uint32_t a) {
    asm volatile("ldmatrix.sync.aligned.m8n8.x4.trans.shared.b16 {%0,%1,%2,%3}, [%4];"
        : "=r"(r[0]), "=r"(r[1]), "=r"(r[2]), "=r"(r[3]) : "r"(a));
}
__device__ __forceinline__ void mma16816(float* d, const uint32_t* a,
                                         uint32_t b0, uint32_t b1) {
    asm volatile(
        "mma.sync.aligned.m16n8k16.row.col.f32.bf16.bf16.f32 "
        "{%0,%1,%2,%3}, {%4,%5,%6,%7}, {%8,%9}, {%0,%1,%2,%3};"
        : "+f"(d[0]), "+f"(d[1]), "+f"(d[2]), "+f"(d[3])
        : "r"(a[0]), "r"(a[1]), "r"(a[2]), "r"(a[3]), "r"(b0), "r"(b1));
}
// split (x,y) into packed bf16x2 hi and lo words
__device__ __forceinline__ void split2(float x, float y, uint32_t& hi, uint32_t& lo) {
    __nv_bfloat16 xh = __float2bfloat16(x);
    __nv_bfloat16 yh = __float2bfloat16(y);
    __nv_bfloat16 xl = __float2bfloat16(x - __bfloat162float(xh));
    __nv_bfloat16 yl = __float2bfloat16(y - __bfloat162float(yh));
    hi = (uint32_t)__bfloat16_as_ushort(xh) | ((uint32_t)__bfloat16_as_ushort(yh) << 16);
    lo = (uint32_t)__bfloat16_as_ushort(xl) | ((uint32_t)__bfloat16_as_ushort(yl) << 16);
}

// ============================================================
// Kernel 1: Wp[b,h,m] = sum_t head_w[h,t] * W[b,t,m] (fp32 scalar),
// written as bf16 hi/lo splits in [h][m] and [m][h] layouts.
// ============================================================
__global__ __launch_bounds__(256) void proj_kernel(const float* __restrict__ W,
                                                   const float* __restrict__ head_w) {
    __shared__ float sA[32][128];  // sA[t][h]
    __shared__ float sB[32][128];  // sB[t][m]
    const int tid = threadIdx.x;
    const int b   = blockIdx.y;
    const int h0  = blockIdx.x * 128;
    const int tx  = tid & 15, ty = tid >> 4;

    float acc[8][8];
#pragma unroll
    for (int i = 0; i < 8; i++)
#pragma unroll
        for (int j = 0; j < 8; j++) acc[i][j] = 0.f;

    const float* Wb = W + (size_t)b * TDIM * MDIM;
    for (int t0 = 0; t0 < TDIM; t0 += 32) {
        {   // head_w[h0+r][t0..t0+31] -> sA[t][r]
            int r = tid >> 1, half = tid & 1;
            const float4* src =
                (const float4*)(head_w + (size_t)(h0 + r) * TDIM + t0 + half * 16);
#pragma unroll
            for (int i = 0; i < 4; i++) {
                float4 v = src[i];
                int tt = half * 16 + i * 4;
                sA[tt + 0][r] = v.x; sA[tt + 1][r] = v.y;
                sA[tt + 2][r] = v.z; sA[tt + 3][r] = v.w;
            }
        }
        {   // W[b][t0+r][*] -> sB[r][*]
            int r = tid >> 3, part = tid & 7;
            const float4* src = (const float4*)(Wb + (size_t)(t0 + r) * MDIM + part * 16);
            float4* dst = (float4*)(&sB[r][part * 16]);
#pragma unroll
            for (int i = 0; i < 4; i++) dst[i] = src[i];
        }
        __syncthreads();
#pragma unroll
        for (int t = 0; t < 32; t++) {
            float a[8], bb[8];
#pragma unroll
            for (int i = 0; i < 8; i++) a[i] = sA[t][ty * 8 + i];
#pragma unroll
            for (int j = 0; j < 8; j++) bb[j] = sB[t][tx * 8 + j];
#pragma unroll
            for (int i = 0; i < 8; i++)
#pragma unroll
                for (int j = 0; j < 8; j++) acc[i][j] = fmaf(a[i], bb[j], acc[i][j]);
        }
        __syncthreads();
    }
#pragma unroll
    for (int i = 0; i < 8; i++) {
        int h = h0 + ty * 8 + i;
#pragma unroll
        for (int j = 0; j < 8; j++) {
            int m = tx * 8 + j;
            float v = acc[i][j];
            __nv_bfloat16 hi = __float2bfloat16(v);
            __nv_bfloat16 lo = __float2bfloat16(v - __bfloat162float(hi));
            size_t pidx = ((size_t)b * HDIM + h) * MDIM + m;
            g_Wp_hi[pidx] = hi;  g_Wp_lo[pidx] = lo;
            size_t tidx = ((size_t)b * MDIM + m) * HDIM + h;
            g_WpT_hi[tidx] = hi; g_WpT_lo[tidx] = lo;
        }
    }
}

// ============================================================
// Kernel 2: fused scores -> softmax -> output via mma.sync (HMMA).
// CTA = (batch b, 128-row n-tile), 256 threads = 8 warps x 16 n-rows.
// ============================================================
#define PADB 136                 // bf16 row stride: 272B -> conflict-free ldmatrix
#define OFF_QH 0                 // 34816 B : Qt hi  [h=128][n=128]  (also out stage)
#define OFF_QL 34816             // 34816 B : Qt lo
#define OFF_KH 69632             // 34816 B : B tile hi [rows=128][k=128]
#define OFF_KL 104448            // 34816 B : B tile lo
#define SMEM_DYN 139264
#define STG_STRIDE 132           // fp32 stage row stride (conflict-free)

__global__ __launch_bounds__(256, 1)
void attn_kernel(const float* __restrict__ H, float* __restrict__ out) {
    extern __shared__ char smem[];
    const uint32_t sbase = smem_u32(smem);

    const int tid = threadIdx.x;
    const int wid = tid >> 5;
    const int lid = tid & 31;
    const int b   = blockIdx.y;
    const int n0  = blockIdx.x * 128;

    const float* Hb = H + (size_t)b * HDIM * NDIM + n0;
    const __nv_bfloat16* KTh = g_WpT_hi + (size_t)b * MDIM * HDIM;
    const __nv_bfloat16* KTl = g_WpT_lo + (size_t)b * MDIM * HDIM;
    const __nv_bfloat16* Wph = g_Wp_hi  + (size_t)b * HDIM * MDIM;
    const __nv_bfloat16* Wpl = g_Wp_lo  + (size_t)b * HDIM * MDIM;

    const uint32_t qhi = sbase + OFF_QH, qlo = sbase + OFF_QL;
    const uint32_t khi = sbase + OFF_KH, klo = sbase + OFF_KL;

    // per-lane ldmatrix geometry
    const int g  = lid >> 3, lr = lid & 7;
    // A (trans, from [k][n] tile): R0:(n0..7,k0..7) R1:(n8..15,k0..7) R2:(n0..7,k8..15) R3:(n8..15,k8..15)
    const int arow = ((g & 2) ? 8 : 0) + lr;        // + kk*16
    const int acol = wid * 16 + ((g & 1) ? 8 : 0);
    const uint32_t a_off = (uint32_t)(arow * PADB + acol) * 2;
    // B (non-trans, from [n][k] tile): R0:(tile0,klo) R1:(tile0,khi) R2:(tile1,klo) R3:(tile1,khi)
    const int brow = ((g >> 1) ? 8 : 0) + lr;       // + tp*16
    const int bcol = (g & 1) ? 8 : 0;               // + kk*16
    const uint32_t b_off = (uint32_t)(brow * PADB + bcol) * 2;

    // ---------------- GEMM1: S[n][m] = sum_h Q[n][h] * WpT[m][h] ----------------
    float sacc[16][4];
#pragma unroll
    for (int t = 0; t < 16; t++)
#pragma unroll
        for (int j = 0; j < 4; j++) sacc[t][j] = 0.f;

    for (int hc = 0; hc < 4; hc++) {
        if (hc) __syncthreads();
        // Q tile: H[b][hc*128+hr][n0+n4] -> smem [hr][n] (coalesced), split hi/lo
#pragma unroll 4
        for (int it = 0; it < 16; it++) {
            int f = it * 256 + tid, hr = f >> 5, n4 = (f & 31) << 2;
            float4 v = *(const float4*)(Hb + (size_t)(hc * 128 + hr) * NDIM + n4);
            uint32_t h01, l01, h23, l23;
            split2(v.x, v.y, h01, l01);
            split2(v.z, v.w, h23, l23);
            uint32_t off = (uint32_t)(hr * PADB + n4) * 2;
            *(uint2*)(smem + OFF_QH + off) = make_uint2(h01, h23);
            *(uint2*)(smem + OFF_QL + off) = make_uint2(l01, l23);
        }
        // K tile: WpT[m][hc*128+c8] -> smem [m][c]
#pragma unroll 4
        for (int it = 0; it < 8; it++) {
            int f = it * 256 + tid, m = f >> 4, c8 = (f & 15) << 3;
            uint32_t off = (uint32_t)(m * PADB + c8) * 2;
            *(uint4*)(smem + OFF_KH + off) =
                *(const uint4*)(KTh + (size_t)m * HDIM + hc * 128 + c8);
            *(uint4*)(smem + OFF_KL + off) =
                *(const uint4*)(KTl + (size_t)m * HDIM + hc * 128 + c8);
        }
        __syncthreads();

#pragma unroll
        for (int kk = 0; kk < 8; kk++) {
            uint32_t ah[4], al[4];
            uint32_t aoff = a_off + (uint32_t)(kk * 16 * PADB) * 2;
            ldsm4t(ah, qhi + aoff);
            ldsm4t(al, qlo + aoff);
#pragma unroll
            for (int tp = 0; tp < 8; tp++) {
                uint32_t boff = b_off + (uint32_t)(tp * 16 * PADB + kk * 16) * 2;
                uint32_t bh[4], bl[4];
                ldsm4(bh, khi + boff);
                ldsm4(bl, klo + boff);
                mma16816(sacc[2 * tp],     ah, bh[0], bh[1]);
                mma16816(sacc[2 * tp],     ah, bl[0], bl[1]);
                mma16816(sacc[2 * tp],     al, bh[0], bh[1]);
                mma16816(sacc[2 * tp + 1], ah, bh[2], bh[3]);
                mma16816(sacc[2 * tp + 1], ah, bl[2], bl[3]);
                mma16816(sacc[2 * tp + 1], al, bh[2], bh[3]);
            }
        }
    }

    // ---------------- softmax over m (in registers) ----------------
    // thread holds rows r=lid/4 and r+8 of its warp's 16; cols m = t*8 + 2q + {0,1}
    float mx0 = -3.4e38f, mx1 = -3.4e38f;
#pragma unroll
    for (int t = 0; t < 16; t++) {
        mx0 = fmaxf(mx0, fmaxf(sacc[t][0], sacc[t][1]));
        mx1 = fmaxf(mx1, fmaxf(sacc[t][2], sacc[t][3]));
    }
    mx0 = fmaxf(mx0, __shfl_xor_sync(0xFFFFFFFFu, mx0, 1));
    mx0 = fmaxf(mx0, __shfl_xor_sync(0xFFFFFFFFu, mx0, 2));
    mx1 = fmaxf(mx1, __shfl_xor_sync(0xFFFFFFFFu, mx1, 1));
    mx1 = fmaxf(mx1, __shfl_xor_sync(0xFFFFFFFFu, mx1, 2));
    float s0 = 0.f, s1 = 0.f;
#pragma unroll
    for (int t = 0; t < 16; t++) {
        sacc[t][0] = __expf(sacc[t][0] - mx0);
        sacc[t][1] = __expf(sacc[t][1] - mx0);
        sacc[t][2] = __expf(sacc[t][2] - mx1);
        sacc[t][3] = __expf(sacc[t][3] - mx1);
        s0 += sacc[t][0] + sacc[t][1];
        s1 += sacc[t][2] + sacc[t][3];
    }
    s0 += __shfl_xor_sync(0xFFFFFFFFu, s0, 1);
    s0 += __shfl_xor_sync(0xFFFFFFFFu, s0, 2);
    s1 += __shfl_xor_sync(0xFFFFFFFFu, s1, 1);
    s1 += __shfl_xor_sync(0xFFFFFFFFu, s1, 2);
    const float r0 = 1.0f / s0, r1 = 1.0f / s1;

    // Repack E (unnormalized) into A-fragments for GEMM2 (k = m), hi/lo split.
    uint32_t eh[8][4], el[8][4];
#pragma unroll
    for (int kk = 0; kk < 8; kk++) {
        int t0 = kk * 2;
        split2(sacc[t0][0],     sacc[t0][1],     eh[kk][0], el[kk][0]);
        split2(sacc[t0][2],     sacc[t0][3],     eh[kk][1], el[kk][1]);
        split2(sacc[t0 + 1][0], sacc[t0 + 1][1], eh[kk][2], el[kk][2]);
        split2(sacc[t0 + 1][2], sacc[t0 + 1][3], eh[kk][3], el[kk][3]);
    }

    // ---------------- GEMM2: C[n][h] = sum_m E[n][m] * Wp[h][m] ----------------
    float* stg = (float*)(smem + OFF_QH);   // stage aliases Q region (67584 B)
    float* outb = out + (size_t)b * HDIM * NDIM;
    const int rr = lid >> 2, qq = lid & 3;

    for (int hc2 = 0; hc2 < 4; hc2++) {
        __syncthreads();   // protect K region + stage from previous uses
        // B tile: Wp[hc2*128+hr][c8] -> smem [hr][c]
#pragma unroll 4
        for (int it = 0; it < 8; it++) {
            int f = it * 256 + tid, hr = f >> 4, c8 = (f & 15) << 3;
            uint32_t off = (uint32_t)(hr * PADB + c8) * 2;
            *(uint4*)(smem + OFF_KH + off) =
                *(const uint4*)(Wph + (size_t)(hc2 * 128 + hr) * MDIM + c8);
            *(uint4*)(smem + OFF_KL + off) =
                *(const uint4*)(Wpl + (size_t)(hc2 * 128 + hr) * MDIM + c8);
        }
        __syncthreads();

        float cacc[16][4];
#pragma unroll
        for (int t = 0; t < 16; t++)
#pragma unroll
            for (int j = 0; j < 4; j++) cacc[t][j] = 0.f;

#pragma unroll
        for (int kk = 0; kk < 8; kk++) {
#pragma unroll
            for (int tp = 0; tp < 8; tp++) {
                uint32_t boff = b_off + (uint32_t)(tp * 16 * PADB + kk * 16) * 2;
                uint32_t bh[4], bl[4];
                ldsm4(bh, khi + boff);
                ldsm4(bl, klo + boff);
                mma16816(cacc[2 * tp],     eh[kk], bh[0], bh[1]);
                mma16816(cacc[2 * tp],     eh[kk], bl[0], bl[1]);
                mma16816(cacc[2 * tp],     el[kk], bh[0], bh[1]);
                mma16816(cacc[2 * tp + 1], eh[kk], bh[2], bh[3]);
                mma16816(cacc[2 * tp + 1], eh[kk], bl[2], bl[3]);
                mma16816(cacc[2 * tp + 1], el[kk], bh[2], bh[3]);
            }
        }

        // scale by 1/sum (thread-local) and stage transposed: stg[h][n]
#pragma unroll
        for (int t = 0; t < 16; t++) {
            int hcl = t * 8 + 2 * qq;
            int n   = wid * 16 + rr;
            stg[(size_t)hcl * STG_STRIDE + n]           = cacc[t][0] * r0;
            stg[(size_t)(hcl + 1) * STG_STRIDE + n]     = cacc[t][1] * r0;
            stg[(size_t)hcl * STG_STRIDE + n + 8]       = cacc[t][2] * r1;
            stg[(size_t)(hcl + 1) * STG_STRIDE + n + 8] = cacc[t][3] * r1;
        }
        __syncthreads();

        // coalesced fp32 store: out[b][hc2*128+hr][n0+n4..]
#pragma unroll 4
        for (int it = 0; it < 16; it++) {
            int f = it * 256 + tid, hr = f >> 5, n4 = (f & 31) << 2;
            float4 v = *(const float4*)(stg + (size_t)hr * STG_STRIDE + n4);
            *(float4*)(outb + (size_t)(hc2 * 128 + hr) * NDIM + n0 + n4) = v;
        }
    }
}

// ============================================================
extern "C" void kernel_launch(void* const* d_in, const int* in_sizes, int n_in,
                              void* d_out, int out_size) {
    const float* H      = (const float*)d_in[0];  // [32,512,64,64]
    const float* W      = (const float*)d_in[1];  // [32,256,128]
    const float* head_w = (const float*)d_in[2];  // [512,256]
    float* out = (float*)d_out;

    cudaFuncSetAttribute(attn_kernel,
                         cudaFuncAttributeMaxDynamicSharedMemorySize, SMEM_DYN);

    proj_kernel<<<dim3(4, B_DIM), 256>>>(W, head_w);
    attn_kernel<<<dim3(NDIM / 128, B_DIM), 256, SMEM_DYN>>>(H, out);
}

// round 6
// speedup vs baseline: 1.1528x; 1.1528x over previous
#include <cuda_runtime.h>
#include <cuda_bf16.h>
#include <cstdint>
#include <cstddef>

#define B_DIM 32
#define HDIM  512
#define NDIM  4096
#define MDIM  128
#define TDIM  256

// __device__ scratch (allocation-free rule). Wp as bf16 hi/lo, two layouts.
__device__ __align__(16) __nv_bfloat16 g_WpT_hi[B_DIM * MDIM * HDIM]; // [b][m][h]
__device__ __align__(16) __nv_bfloat16 g_WpT_lo[B_DIM * MDIM * HDIM];
__device__ __align__(16) __nv_bfloat16 g_Wp_hi [B_DIM * HDIM * MDIM]; // [b][h][m]
__device__ __align__(16) __nv_bfloat16 g_Wp_lo [B_DIM * HDIM * MDIM];

// ---------------- helpers (all non-arch-specific PTX) ----------------
__device__ __forceinline__ uint32_t smem_u32(const void* p) {
    uint32_t a;
    asm("{ .reg .u64 t; cvta.to.shared.u64 t, %1; cvt.u32.u64 %0, t; }"
        : "=r"(a) : "l"(p));
    return a;
}
__device__ __forceinline__ void ldsm4(uint32_t* r, uint32_t a) {
    asm volatile("ldmatrix.sync.aligned.m8n8.x4.shared.b16 {%0,%1,%2,%3}, [%4];"
        : "=r"(r[0]), "=r"(r[1]), "=r"(r[2]), "=r"(r[3]) : "r"(a));
}
__device__ __forceinline__ void ldsm4t(uint32_t* r, uint32_t a) {
    asm volatile("ldmatrix.sync.aligned.m8n8.x4.trans.shared.b16 {%0,%1,%2,%3}, [%4];"
        : "=r"(r[0]), "=r"(r[1]), "=r"(r[2]), "=r"(r[3]) : "r"(a));
}
__device__ __forceinline__ void mma16816(float* d, const uint32_t* a,
                                         uint32_t b0, uint32_t b1) {
    asm volatile(
        "mma.sync.aligned.m16n8k16.row.col.f32.bf16.bf16.f32 "
        "{%0,%1,%2,%3}, {%4,%5,%6,%7}, {%8,%9}, {%0,%1,%2,%3};"
        : "+f"(d[0]), "+f"(d[1]), "+f"(d[2]), "+f"(d[3])
        : "r"(a[0]), "r"(a[1]), "r"(a[2]), "r"(a[3]), "r"(b0), "r"(b1));
}
__device__ __forceinline__ void split2(float x, float y, uint32_t& hi, uint32_t& lo) {
    __nv_bfloat16 xh = __float2bfloat16(x);
    __nv_bfloat16 yh = __float2bfloat16(y);
    __nv_bfloat16 xl = __float2bfloat16(x - __bfloat162float(xh));
    __nv_bfloat16 yl = __float2bfloat16(y - __bfloat162float(yh));
    hi = (uint32_t)__bfloat16_as_ushort(xh) | ((uint32_t)__bfloat16_as_ushort(yh) << 16);
    lo = (uint32_t)__bfloat16_as_ushort(xl) | ((uint32_t)__bfloat16_as_ushort(yl) << 16);
}
#define CP_ASYNC16(dst, src)                                                   \
    asm volatile("cp.async.cg.shared.global [%0], [%1], 16;"                   \
                 :: "r"(dst), "l"(src))
#define CP_COMMIT() asm volatile("cp.async.commit_group;" ::: "memory")
#define CP_WAIT(n)  asm volatile("cp.async.wait_group %0;" :: "n"(n) : "memory")

// ============================================================
// Kernel 1: Wp[b,h,m] = sum_t head_w[h,t] * W[b,t,m] (fp32 scalar),
// written as bf16 hi/lo splits in [h][m] and [m][h] layouts.
// ============================================================
__global__ __launch_bounds__(256) void proj_kernel(const float* __restrict__ W,
                                                   const float* __restrict__ head_w) {
    __shared__ float sA[32][128];  // sA[t][h]
    __shared__ float sB[32][128];  // sB[t][m]
    const int tid = threadIdx.x;
    const int b   = blockIdx.y;
    const int h0  = blockIdx.x * 128;
    const int tx  = tid & 15, ty = tid >> 4;

    float acc[8][8];
#pragma unroll
    for (int i = 0; i < 8; i++)
#pragma unroll
        for (int j = 0; j < 8; j++) acc[i][j] = 0.f;

    const float* Wb = W + (size_t)b * TDIM * MDIM;
    for (int t0 = 0; t0 < TDIM; t0 += 32) {
        {
            int r = tid >> 1, half = tid & 1;
            const float4* src =
                (const float4*)(head_w + (size_t)(h0 + r) * TDIM + t0 + half * 16);
#pragma unroll
            for (int i = 0; i < 4; i++) {
                float4 v = src[i];
                int tt = half * 16 + i * 4;
                sA[tt + 0][r] = v.x; sA[tt + 1][r] = v.y;
                sA[tt + 2][r] = v.z; sA[tt + 3][r] = v.w;
            }
        }
        {
            int r = tid >> 3, part = tid & 7;
            const float4* src = (const float4*)(Wb + (size_t)(t0 + r) * MDIM + part * 16);
            float4* dst = (float4*)(&sB[r][part * 16]);
#pragma unroll
            for (int i = 0; i < 4; i++) dst[i] = src[i];
        }
        __syncthreads();
#pragma unroll
        for (int t = 0; t < 32; t++) {
            float a[8], bb[8];
#pragma unroll
            for (int i = 0; i < 8; i++) a[i] = sA[t][ty * 8 + i];
#pragma unroll
            for (int j = 0; j < 8; j++) bb[j] = sB[t][tx * 8 + j];
#pragma unroll
            for (int i = 0; i < 8; i++)
#pragma unroll
                for (int j = 0; j < 8; j++) acc[i][j] = fmaf(a[i], bb[j], acc[i][j]);
        }
        __syncthreads();
    }
#pragma unroll
    for (int i = 0; i < 8; i++) {
        int h = h0 + ty * 8 + i;
#pragma unroll
        for (int j = 0; j < 8; j++) {
            int m = tx * 8 + j;
            float v = acc[i][j];
            __nv_bfloat16 hi = __float2bfloat16(v);
            __nv_bfloat16 lo = __float2bfloat16(v - __bfloat162float(hi));
            size_t pidx = ((size_t)b * HDIM + h) * MDIM + m;
            g_Wp_hi[pidx] = hi;  g_Wp_lo[pidx] = lo;
            size_t tidx = ((size_t)b * MDIM + m) * HDIM + h;
            g_WpT_hi[tidx] = hi; g_WpT_lo[tidx] = lo;
        }
    }
}

// ============================================================
// Kernel 2: fused scores -> softmax -> output, cp.async pipelined.
// CTA = (batch b, 128-row n-tile), 256 threads = 8 warps x 16 n-rows.
//
// SMEM union map (bytes):
//   GEMM1: KB0 @0 (36864), KB1 @36864, QH @73728 (17408), QL @91136,
//          QF0 @139264 (33792), QF1 @173056
//   GEMM2: WB0 @0 (69632: hi+lo), WB1 @69632, STG @139264 (67584)
// ============================================================
#define PADB 136     // bf16 col pad for 128-wide tiles
#define PADK 72      // bf16 col pad for 64-wide K tiles
#define PADF 132     // fp32 col pad
#define OFF_KB  0
#define KB_SZ   36864           // per buffer: hi 18432 + lo 18432
#define OFF_QHH 73728
#define OFF_QLL 91136
#define OFF_WB  0
#define WB_SZ   69632           // per buffer: hi 34816 + lo 34816
#define OFF_QF  139264
#define QF_SZ   33792
#define OFF_STG 139264
#define STG_STRIDE 132
#define SMEM_DYN 206848

__global__ __launch_bounds__(256, 1)
void attn_kernel(const float* __restrict__ H, float* __restrict__ out) {
    extern __shared__ char smem[];
    const uint32_t sbase = smem_u32(smem);

    const int tid = threadIdx.x;
    const int wid = tid >> 5;
    const int lid = tid & 31;
    const int b   = blockIdx.y;
    const int n0  = blockIdx.x * 128;

    const float* Hb = H + (size_t)b * HDIM * NDIM + n0;
    const __nv_bfloat16* KTh = g_WpT_hi + (size_t)b * MDIM * HDIM;
    const __nv_bfloat16* KTl = g_WpT_lo + (size_t)b * MDIM * HDIM;
    const __nv_bfloat16* Wph = g_Wp_hi  + (size_t)b * HDIM * MDIM;
    const __nv_bfloat16* Wpl = g_Wp_lo  + (size_t)b * HDIM * MDIM;

    // per-lane ldmatrix geometry (same fragment mapping as the passing R5)
    const int g  = lid >> 3, lr = lid & 7;
    const int arow = ((g & 2) ? 8 : 0) + lr;                // + kk*16 (k rows)
    const int acol = wid * 16 + ((g & 1) ? 8 : 0);          // n cols
    const uint32_t a_off = (uint32_t)(arow * PADB + acol) * 2;
    const int brow = ((g >> 1) ? 8 : 0) + lr;               // + tp*16
    const int bcol = (g & 1) ? 8 : 0;                       // + kk*16
    const uint32_t b_off_k = (uint32_t)(brow * PADK + bcol) * 2;  // GEMM1 (PADK)
    const uint32_t b_off_m = (uint32_t)(brow * PADB + bcol) * 2;  // GEMM2 (PADB)

    // ---- cp.async issue helpers (lambdas) ----
    auto issue_q = [&](int hc, int p) {
        uint32_t dbase = sbase + OFF_QF + p * QF_SZ;
#pragma unroll
        for (int it = 0; it < 8; it++) {
            int f = it * 256 + tid, hr = f >> 5, c4 = (f & 31) << 2;
            uint32_t dst = dbase + (uint32_t)(hr * PADF + c4) * 4;
            const float* src = Hb + (size_t)(hc * 64 + hr) * NDIM + c4;
            CP_ASYNC16(dst, src);
        }
    };
    auto issue_k = [&](int hc, int p) {
        uint32_t dh = sbase + OFF_KB + p * KB_SZ;
        uint32_t dl = dh + 18432;
        int k0 = hc * 64;
#pragma unroll
        for (int it = 0; it < 4; it++) {
            int f = it * 256 + tid, m = f >> 3, c8 = (f & 7) << 3;
            uint32_t o = (uint32_t)(m * PADK + c8) * 2;
            CP_ASYNC16(dh + o, KTh + (size_t)m * HDIM + k0 + c8);
            CP_ASYNC16(dl + o, KTl + (size_t)m * HDIM + k0 + c8);
        }
    };
    auto issue_w = [&](int hc2, int p) {
        uint32_t dh = sbase + OFF_WB + p * WB_SZ;
        uint32_t dl = dh + 34816;
#pragma unroll
        for (int it = 0; it < 8; it++) {
            int f = it * 256 + tid, hr = f >> 4, c8 = (f & 15) << 3;
            uint32_t o = (uint32_t)(hr * PADB + c8) * 2;
            CP_ASYNC16(dh + o, Wph + (size_t)(hc2 * 128 + hr) * MDIM + c8);
            CP_ASYNC16(dl + o, Wpl + (size_t)(hc2 * 128 + hr) * MDIM + c8);
        }
    };

    // ---------------- GEMM1: S[n][m] = sum_h Q[n][h] * WpT[m][h] ----------------
    float sacc[16][4];
#pragma unroll
    for (int t = 0; t < 16; t++)
#pragma unroll
        for (int j = 0; j < 4; j++) sacc[t][j] = 0.f;

    // prologue: chunk 0 in flight
    issue_q(0, 0); issue_k(0, 0); CP_COMMIT();

    const uint32_t qhi = sbase + OFF_QHH, qlo = sbase + OFF_QLL;

    for (int hc = 0; hc < 8; hc++) {
        const int p = hc & 1;
        __syncthreads();                 // prev MMA done: buffers p^1, QH/QL free
        if (hc < 7) {
            issue_q(hc + 1, p ^ 1); issue_k(hc + 1, p ^ 1); CP_COMMIT();
            CP_WAIT(1);
        } else {
            CP_WAIT(0);
        }
        __syncthreads();                 // chunk hc data visible to all warps

        // convert QF32[p] -> QH/QL (bf16 hi/lo), rows = k(0..63), cols = n
        {
            const float* qf = (const float*)(smem + OFF_QF + p * QF_SZ);
#pragma unroll
            for (int it = 0; it < 8; it++) {
                int f = it * 256 + tid, hr = f >> 5, c4 = (f & 31) << 2;
                float4 v = *(const float4*)(qf + (size_t)hr * PADF + c4);
                uint32_t h01, l01, h23, l23;
                split2(v.x, v.y, h01, l01);
                split2(v.z, v.w, h23, l23);
                uint32_t off = (uint32_t)(hr * PADB + c4) * 2;
                *(uint2*)(smem + OFF_QHH + off) = make_uint2(h01, h23);
                *(uint2*)(smem + OFF_QLL + off) = make_uint2(l01, l23);
            }
        }
        __syncthreads();

        const uint32_t khi = sbase + OFF_KB + p * KB_SZ;
        const uint32_t klo = khi + 18432;
#pragma unroll
        for (int kk = 0; kk < 4; kk++) {
            uint32_t ah[4], al[4];
            uint32_t aoff = a_off + (uint32_t)(kk * 16 * PADB) * 2;
            ldsm4t(ah, qhi + aoff);
            ldsm4t(al, qlo + aoff);
#pragma unroll
            for (int tp = 0; tp < 8; tp++) {
                uint32_t boff = b_off_k + (uint32_t)(tp * 16 * PADK + kk * 16) * 2;
                uint32_t bh[4], bl[4];
                ldsm4(bh, khi + boff);
                ldsm4(bl, klo + boff);
                mma16816(sacc[2 * tp],     ah, bh[0], bh[1]);
                mma16816(sacc[2 * tp],     ah, bl[0], bl[1]);
                mma16816(sacc[2 * tp],     al, bh[0], bh[1]);
                mma16816(sacc[2 * tp + 1], ah, bh[2], bh[3]);
                mma16816(sacc[2 * tp + 1], ah, bl[2], bl[3]);
                mma16816(sacc[2 * tp + 1], al, bh[2], bh[3]);
            }
        }
    }

    // prefetch GEMM2 chunk 0 (overlaps softmax); GEMM1 regions are dead
    __syncthreads();
    issue_w(0, 0); CP_COMMIT();

    // ---------------- softmax over m (registers only) ----------------
    float mx0 = -3.4e38f, mx1 = -3.4e38f;
#pragma unroll
    for (int t = 0; t < 16; t++) {
        mx0 = fmaxf(mx0, fmaxf(sacc[t][0], sacc[t][1]));
        mx1 = fmaxf(mx1, fmaxf(sacc[t][2], sacc[t][3]));
    }
    mx0 = fmaxf(mx0, __shfl_xor_sync(0xFFFFFFFFu, mx0, 1));
    mx0 = fmaxf(mx0, __shfl_xor_sync(0xFFFFFFFFu, mx0, 2));
    mx1 = fmaxf(mx1, __shfl_xor_sync(0xFFFFFFFFu, mx1, 1));
    mx1 = fmaxf(mx1, __shfl_xor_sync(0xFFFFFFFFu, mx1, 2));
    float s0 = 0.f, s1 = 0.f;
#pragma unroll
    for (int t = 0; t < 16; t++) {
        sacc[t][0] = __expf(sacc[t][0] - mx0);
        sacc[t][1] = __expf(sacc[t][1] - mx0);
        sacc[t][2] = __expf(sacc[t][2] - mx1);
        sacc[t][3] = __expf(sacc[t][3] - mx1);
        s0 += sacc[t][0] + sacc[t][1];
        s1 += sacc[t][2] + sacc[t][3];
    }
    s0 += __shfl_xor_sync(0xFFFFFFFFu, s0, 1);
    s0 += __shfl_xor_sync(0xFFFFFFFFu, s0, 2);
    s1 += __shfl_xor_sync(0xFFFFFFFFu, s1, 1);
    s1 += __shfl_xor_sync(0xFFFFFFFFu, s1, 2);
    const float r0 = 1.0f / s0, r1 = 1.0f / s1;

    // Repack unnormalized E into GEMM2 A-fragments (k = m), hi/lo split.
    uint32_t eh[8][4], el[8][4];
#pragma unroll
    for (int kk = 0; kk < 8; kk++) {
        int t0 = kk * 2;
        split2(sacc[t0][0],     sacc[t0][1],     eh[kk][0], el[kk][0]);
        split2(sacc[t0][2],     sacc[t0][3],     eh[kk][1], el[kk][1]);
        split2(sacc[t0 + 1][0], sacc[t0 + 1][1], eh[kk][2], el[kk][2]);
        split2(sacc[t0 + 1][2], sacc[t0 + 1][3], eh[kk][3], el[kk][3]);
    }

    // ---------------- GEMM2: C[n][h] = sum_m E[n][m] * Wp[h][m] ----------------
    float* stg = (float*)(smem + OFF_STG);
    float* outb = out + (size_t)b * HDIM * NDIM;
    const int rr = lid >> 2, qq = lid & 3;

    for (int hc2 = 0; hc2 < 4; hc2++) {
        const int p = hc2 & 1;
        if (hc2 < 3) {
            issue_w(hc2 + 1, p ^ 1); CP_COMMIT();
            CP_WAIT(1);
        } else {
            CP_WAIT(0);
        }
        __syncthreads();                 // chunk hc2 B tile visible

        float cacc[16][4];
#pragma unroll
        for (int t = 0; t < 16; t++)
#pragma unroll
            for (int j = 0; j < 4; j++) cacc[t][j] = 0.f;

        const uint32_t whi = sbase + OFF_WB + p * WB_SZ;
        const uint32_t wlo = whi + 34816;
#pragma unroll
        for (int kk = 0; kk < 8; kk++) {
#pragma unroll
            for (int tp = 0; tp < 8; tp++) {
                uint32_t boff = b_off_m + (uint32_t)(tp * 16 * PADB + kk * 16) * 2;
                uint32_t bh[4], bl[4];
                ldsm4(bh, whi + boff);
                ldsm4(bl, wlo + boff);
                mma16816(cacc[2 * tp],     eh[kk], bh[0], bh[1]);
                mma16816(cacc[2 * tp],     eh[kk], bl[0], bl[1]);
                mma16816(cacc[2 * tp],     el[kk], bh[0], bh[1]);
                mma16816(cacc[2 * tp + 1], eh[kk], bh[2], bh[3]);
                mma16816(cacc[2 * tp + 1], eh[kk], bl[2], bl[3]);
                mma16816(cacc[2 * tp + 1], el[kk], bh[2], bh[3]);
            }
        }

        // scale by 1/sum and stage transposed: stg[h_local][n]
#pragma unroll
        for (int t = 0; t < 16; t++) {
            int hcl = t * 8 + 2 * qq;
            int n   = wid * 16 + rr;
            stg[(size_t)hcl * STG_STRIDE + n]           = cacc[t][0] * r0;
            stg[(size_t)(hcl + 1) * STG_STRIDE + n]     = cacc[t][1] * r0;
            stg[(size_t)hcl * STG_STRIDE + n + 8]       = cacc[t][2] * r1;
            stg[(size_t)(hcl + 1) * STG_STRIDE + n + 8] = cacc[t][3] * r1;
        }
        __syncthreads();

        // coalesced fp32 store: out[b][hc2*128+hr][n0+...]
#pragma unroll 4
        for (int it = 0; it < 16; it++) {
            int f = it * 256 + tid, hr = f >> 5, n4 = (f & 31) << 2;
            float4 v = *(const float4*)(stg + (size_t)hr * STG_STRIDE + n4);
            *(float4*)(outb + (size_t)(hc2 * 128 + hr) * NDIM + n0 + n4) = v;
        }
        __syncthreads();                 // stage + B buffer free for next iter
    }
}

// ============================================================
extern "C" void kernel_launch(void* const* d_in, const int* in_sizes, int n_in,
                              void* d_out, int out_size) {
    const float* H      = (const float*)d_in[0];  // [32,512,64,64]
    const float* W      = (const float*)d_in[1];  // [32,256,128]
    const float* head_w = (const float*)d_in[2];  // [512,256]
    float* out = (float*)d_out;

    cudaFuncSetAttribute(attn_kernel,
                         cudaFuncAttributeMaxDynamicSharedMemorySize, SMEM_DYN);

    proj_kernel<<<dim3(4, B_DIM), 256>>>(W, head_w);
    attn_kernel<<<dim3(NDIM / 128, B_DIM), 256, SMEM_DYN>>>(H, out);
}

// round 7
// speedup vs baseline: 1.3007x; 1.1283x over previous
#include <cuda_runtime.h>
#include <cuda_bf16.h>
#include <cstdint>
#include <cstddef>

#define B_DIM 32
#define HDIM  512
#define NDIM  4096
#define MDIM  128
#define TDIM  256

// __device__ scratch (allocation-free rule). Wp as bf16 hi/lo, two layouts.
__device__ __align__(16) __nv_bfloat16 g_WpT_hi[B_DIM * MDIM * HDIM]; // [b][m][h]
__device__ __align__(16) __nv_bfloat16 g_WpT_lo[B_DIM * MDIM * HDIM];
__device__ __align__(16) __nv_bfloat16 g_Wp_hi [B_DIM * HDIM * MDIM]; // [b][h][m]
__device__ __align__(16) __nv_bfloat16 g_Wp_lo [B_DIM * HDIM * MDIM];

// ---------------- helpers (all non-arch-specific PTX) ----------------
__device__ __forceinline__ uint32_t smem_u32(const void* p) {
    uint32_t a;
    asm("{ .reg .u64 t; cvta.to.shared.u64 t, %1; cvt.u32.u64 %0, t; }"
        : "=r"(a) : "l"(p));
    return a;
}
__device__ __forceinline__ void ldsm4(uint32_t* r, uint32_t a) {
    asm volatile("ldmatrix.sync.aligned.m8n8.x4.shared.b16 {%0,%1,%2,%3}, [%4];"
        : "=r"(r[0]), "=r"(r[1]), "=r"(r[2]), "=r"(r[3]) : "r"(a));
}
__device__ __forceinline__ void ldsm4t(uint32_t* r, uint32_t a) {
    asm volatile("ldmatrix.sync.aligned.m8n8.x4.trans.shared.b16 {%0,%1,%2,%3}, [%4];"
        : "=r"(r[0]), "=r"(r[1]), "=r"(r[2]), "=r"(r[3]) : "r"(a));
}
__device__ __forceinline__ void mma16816(float* d, const uint32_t* a,
                                         uint32_t b0, uint32_t b1) {
    asm volatile(
        "mma.sync.aligned.m16n8k16.row.col.f32.bf16.bf16.f32 "
        "{%0,%1,%2,%3}, {%4,%5,%6,%7}, {%8,%9}, {%0,%1,%2,%3};"
        : "+f"(d[0]), "+f"(d[1]), "+f"(d[2]), "+f"(d[3])
        : "r"(a[0]), "r"(a[1]), "r"(a[2]), "r"(a[3]), "r"(b0), "r"(b1));
}
__device__ __forceinline__ void split2(float x, float y, uint32_t& hi, uint32_t& lo) {
    __nv_bfloat16 xh = __float2bfloat16(x);
    __nv_bfloat16 yh = __float2bfloat16(y);
    __nv_bfloat16 xl = __float2bfloat16(x - __bfloat162float(xh));
    __nv_bfloat16 yl = __float2bfloat16(y - __bfloat162float(yh));
    hi = (uint32_t)__bfloat16_as_ushort(xh) | ((uint32_t)__bfloat16_as_ushort(yh) << 16);
    lo = (uint32_t)__bfloat16_as_ushort(xl) | ((uint32_t)__bfloat16_as_ushort(yl) << 16);
}
#define CP_ASYNC16(dst, src)                                                   \
    asm volatile("cp.async.cg.shared.global [%0], [%1], 16;"                   \
                 :: "r"(dst), "l"(src))
#define CP_COMMIT() asm volatile("cp.async.commit_group;" ::: "memory")
#define CP_WAIT(n)  asm volatile("cp.async.wait_group %0;" :: "n"(n) : "memory")

// ============================================================
// Kernel 1: Wp[b,h,m] = sum_t head_w[h,t] * W[b,t,m] (fp32 scalar),
// written as bf16 hi/lo splits in [h][m] and [m][h] layouts.
// ============================================================
__global__ __launch_bounds__(256) void proj_kernel(const float* __restrict__ W,
                                                   const float* __restrict__ head_w) {
    __shared__ float sA[32][128];  // sA[t][h]
    __shared__ float sB[32][128];  // sB[t][m]
    const int tid = threadIdx.x;
    const int b   = blockIdx.y;
    const int h0  = blockIdx.x * 128;
    const int tx  = tid & 15, ty = tid >> 4;

    float acc[8][8];
#pragma unroll
    for (int i = 0; i < 8; i++)
#pragma unroll
        for (int j = 0; j < 8; j++) acc[i][j] = 0.f;

    const float* Wb = W + (size_t)b * TDIM * MDIM;
    for (int t0 = 0; t0 < TDIM; t0 += 32) {
        {
            int r = tid >> 1, half = tid & 1;
            const float4* src =
                (const float4*)(head_w + (size_t)(h0 + r) * TDIM + t0 + half * 16);
#pragma unroll
            for (int i = 0; i < 4; i++) {
                float4 v = src[i];
                int tt = half * 16 + i * 4;
                sA[tt + 0][r] = v.x; sA[tt + 1][r] = v.y;
                sA[tt + 2][r] = v.z; sA[tt + 3][r] = v.w;
            }
        }
        {
            int r = tid >> 3, part = tid & 7;
            const float4* src = (const float4*)(Wb + (size_t)(t0 + r) * MDIM + part * 16);
            float4* dst = (float4*)(&sB[r][part * 16]);
#pragma unroll
            for (int i = 0; i < 4; i++) dst[i] = src[i];
        }
        __syncthreads();
#pragma unroll
        for (int t = 0; t < 32; t++) {
            float a[8], bb[8];
#pragma unroll
            for (int i = 0; i < 8; i++) a[i] = sA[t][ty * 8 + i];
#pragma unroll
            for (int j = 0; j < 8; j++) bb[j] = sB[t][tx * 8 + j];
#pragma unroll
            for (int i = 0; i < 8; i++)
#pragma unroll
                for (int j = 0; j < 8; j++) acc[i][j] = fmaf(a[i], bb[j], acc[i][j]);
        }
        __syncthreads();
    }
#pragma unroll
    for (int i = 0; i < 8; i++) {
        int h = h0 + ty * 8 + i;
#pragma unroll
        for (int j = 0; j < 8; j++) {
            int m = tx * 8 + j;
            float v = acc[i][j];
            __nv_bfloat16 hi = __float2bfloat16(v);
            __nv_bfloat16 lo = __float2bfloat16(v - __bfloat162float(hi));
            size_t pidx = ((size_t)b * HDIM + h) * MDIM + m;
            g_Wp_hi[pidx] = hi;  g_Wp_lo[pidx] = lo;
            size_t tidx = ((size_t)b * MDIM + m) * HDIM + h;
            g_WpT_hi[tidx] = hi; g_WpT_lo[tidx] = lo;
        }
    }
}

// ============================================================
// Kernel 2: fused scores -> softmax -> output.
// CTA = (batch b, 64-row n-tile), 128 threads = 4 warps x 16 n-rows.
// 2 CTAs per SM (smem ~90 KB each) so barriers of one CTA are hidden
// by the other CTA's MMA work.
//
// SMEM union (bytes):
//   GEMM1: KB0 @0 (36864 = hi 18432 + lo 18432), KB1 @36864,
//          QH @73728 (9216), QL @82944        -> end 92160
//   GEMM2: WB0 @0 (34816 = hi 17408 + lo 17408), WB1 @34816,
//          STG @69632 (17408)                 -> end 87040
// ============================================================
#define PADQ 72      // Q tile [k=64][n=64] bf16 row stride
#define PADK 72      // K tile [m=128][k=64] bf16 row stride
#define PADW 136     // W tile [h=64][m=128] bf16 row stride
#define STGS 68      // out stage [h=64][n=64] fp32 row stride
#define OFF_KB  0
#define KB_SZ   36864
#define OFF_QH  73728
#define OFF_QL  82944
#define OFF_WB  0
#define WB_SZ   34816
#define OFF_STG 69632
#define SMEM_DYN 92160

__global__ __launch_bounds__(128, 2)
void attn_kernel(const float* __restrict__ H, float* __restrict__ out) {
    extern __shared__ char smem[];
    const uint32_t sbase = smem_u32(smem);

    const int tid = threadIdx.x;
    const int wid = tid >> 5;
    const int lid = tid & 31;
    const int b   = blockIdx.y;
    const int n0  = blockIdx.x * 64;

    const float* Hb = H + (size_t)b * HDIM * NDIM + n0;
    const __nv_bfloat16* KTh = g_WpT_hi + (size_t)b * MDIM * HDIM;
    const __nv_bfloat16* KTl = g_WpT_lo + (size_t)b * MDIM * HDIM;
    const __nv_bfloat16* Wph = g_Wp_hi  + (size_t)b * HDIM * MDIM;
    const __nv_bfloat16* Wpl = g_Wp_lo  + (size_t)b * HDIM * MDIM;

    // per-lane ldmatrix geometry (identical fragment mapping to passing R6)
    const int g  = lid >> 3, lr = lid & 7;
    const int arow = ((g & 2) ? 8 : 0) + lr;                 // + kk*16
    const int acol = wid * 16 + ((g & 1) ? 8 : 0);           // n (0..63)
    const uint32_t a_off = (uint32_t)(arow * PADQ + acol) * 2;
    const int brow = ((g >> 1) ? 8 : 0) + lr;                // + tp*16
    const int bcol = (g & 1) ? 8 : 0;                        // + kk*16
    const uint32_t b_off_k = (uint32_t)(brow * PADK + bcol) * 2;
    const uint32_t b_off_w = (uint32_t)(brow * PADW + bcol) * 2;

    // ---- async issue helpers ----
    auto issue_k = [&](int hc, int p) {
        uint32_t dh = sbase + OFF_KB + p * KB_SZ;
        uint32_t dl = dh + 18432;
        int k0 = hc * 64;
#pragma unroll
        for (int it = 0; it < 8; it++) {
            int f = it * 128 + tid, m = f >> 3, c8 = (f & 7) << 3;
            uint32_t o = (uint32_t)(m * PADK + c8) * 2;
            CP_ASYNC16(dh + o, KTh + (size_t)m * HDIM + k0 + c8);
            CP_ASYNC16(dl + o, KTl + (size_t)m * HDIM + k0 + c8);
        }
    };
    auto issue_w = [&](int hc2, int p) {
        uint32_t dh = sbase + OFF_WB + p * WB_SZ;
        uint32_t dl = dh + 17408;
#pragma unroll
        for (int it = 0; it < 8; it++) {
            int f = it * 128 + tid, hr = f >> 4, c8 = (f & 15) << 3;
            uint32_t o = (uint32_t)(hr * PADW + c8) * 2;
            CP_ASYNC16(dh + o, Wph + (size_t)(hc2 * 64 + hr) * MDIM + c8);
            CP_ASYNC16(dl + o, Wpl + (size_t)(hc2 * 64 + hr) * MDIM + c8);
        }
    };
    // Q chunk -> registers (8 float4 per thread = rows hr=f>>4, cols (f&15)*4)
    auto ldg_q = [&](int hc, float4* qv) {
#pragma unroll
        for (int it = 0; it < 8; it++) {
            int f = it * 128 + tid, hr = f >> 4, c4 = (f & 15) << 2;
            qv[it] = *(const float4*)(Hb + (size_t)(hc * 64 + hr) * NDIM + c4);
        }
    };

    // ---------------- GEMM1: S[n][m] = sum_h Q[n][h] * WpT[m][h] ----------------
    float sacc[16][4];
#pragma unroll
    for (int t = 0; t < 16; t++)
#pragma unroll
        for (int j = 0; j < 4; j++) sacc[t][j] = 0.f;

    float4 qv[8];
    issue_k(0, 0); CP_COMMIT();
    ldg_q(0, qv);

    const uint32_t qhi = sbase + OFF_QH, qlo = sbase + OFF_QL;

    for (int hc = 0; hc < 8; hc++) {
        const int p = hc & 1;
        // convert current Q registers -> QH/QL (tile rows = k, cols = n)
#pragma unroll
        for (int it = 0; it < 8; it++) {
            int f = it * 128 + tid, hr = f >> 4, c4 = (f & 15) << 2;
            uint32_t h01, l01, h23, l23;
            split2(qv[it].x, qv[it].y, h01, l01);
            split2(qv[it].z, qv[it].w, h23, l23);
            uint32_t off = (uint32_t)(hr * PADQ + c4) * 2;
            *(uint2*)(smem + OFF_QH + off) = make_uint2(h01, h23);
            *(uint2*)(smem + OFF_QL + off) = make_uint2(l01, l23);
        }
        CP_WAIT(0);                      // K chunk hc resident
        __syncthreads();                 // Q + K visible to all warps
        if (hc < 7) {
            issue_k(hc + 1, p ^ 1); CP_COMMIT();
            ldg_q(hc + 1, qv);           // overlaps MMA below
        }

        const uint32_t khi = sbase + OFF_KB + p * KB_SZ;
        const uint32_t klo = khi + 18432;
#pragma unroll
        for (int kk = 0; kk < 4; kk++) {
            uint32_t ah[4], al[4];
            uint32_t aoff = a_off + (uint32_t)(kk * 16 * PADQ) * 2;
            ldsm4t(ah, qhi + aoff);
            ldsm4t(al, qlo + aoff);
#pragma unroll
            for (int tp = 0; tp < 8; tp++) {
                uint32_t boff = b_off_k + (uint32_t)(tp * 16 * PADK + kk * 16) * 2;
                uint32_t bh[4], bl[4];
                ldsm4(bh, khi + boff);
                ldsm4(bl, klo + boff);
                mma16816(sacc[2 * tp],     ah, bh[0], bh[1]);
                mma16816(sacc[2 * tp],     ah, bl[0], bl[1]);
                mma16816(sacc[2 * tp],     al, bh[0], bh[1]);
                mma16816(sacc[2 * tp + 1], ah, bh[2], bh[3]);
                mma16816(sacc[2 * tp + 1], ah, bl[2], bl[3]);
                mma16816(sacc[2 * tp + 1], al, bh[2], bh[3]);
            }
        }
        __syncthreads();                 // QH/QL + KB[p] free for reuse
    }

    // prefetch GEMM2 chunk 0 (WB aliases dead KB region); overlaps softmax
    issue_w(0, 0); CP_COMMIT();

    // ---------------- softmax over m (registers only) ----------------
    float mx0 = -3.4e38f, mx1 = -3.4e38f;
#pragma unroll
    for (int t = 0; t < 16; t++) {
        mx0 = fmaxf(mx0, fmaxf(sacc[t][0], sacc[t][1]));
        mx1 = fmaxf(mx1, fmaxf(sacc[t][2], sacc[t][3]));
    }
    mx0 = fmaxf(mx0, __shfl_xor_sync(0xFFFFFFFFu, mx0, 1));
    mx0 = fmaxf(mx0, __shfl_xor_sync(0xFFFFFFFFu, mx0, 2));
    mx1 = fmaxf(mx1, __shfl_xor_sync(0xFFFFFFFFu, mx1, 1));
    mx1 = fmaxf(mx1, __shfl_xor_sync(0xFFFFFFFFu, mx1, 2));
    float s0 = 0.f, s1 = 0.f;
#pragma unroll
    for (int t = 0; t < 16; t++) {
        sacc[t][0] = __expf(sacc[t][0] - mx0);
        sacc[t][1] = __expf(sacc[t][1] - mx0);
        sacc[t][2] = __expf(sacc[t][2] - mx1);
        sacc[t][3] = __expf(sacc[t][3] - mx1);
        s0 += sacc[t][0] + sacc[t][1];
        s1 += sacc[t][2] + sacc[t][3];
    }
    s0 += __shfl_xor_sync(0xFFFFFFFFu, s0, 1);
    s0 += __shfl_xor_sync(0xFFFFFFFFu, s0, 2);
    s1 += __shfl_xor_sync(0xFFFFFFFFu, s1, 1);
    s1 += __shfl_xor_sync(0xFFFFFFFFu, s1, 2);
    const float r0 = 1.0f / s0, r1 = 1.0f / s1;

    // Repack unnormalized E into GEMM2 A-fragments (k = m), hi/lo split.
    uint32_t eh[8][4], el[8][4];
#pragma unroll
    for (int kk = 0; kk < 8; kk++) {
        int t0 = kk * 2;
        split2(sacc[t0][0],     sacc[t0][1],     eh[kk][0], el[kk][0]);
        split2(sacc[t0][2],     sacc[t0][3],     eh[kk][1], el[kk][1]);
        split2(sacc[t0 + 1][0], sacc[t0 + 1][1], eh[kk][2], el[kk][2]);
        split2(sacc[t0 + 1][2], sacc[t0 + 1][3], eh[kk][3], el[kk][3]);
    }

    // ---------------- GEMM2: C[n][h] = sum_m E[n][m] * Wp[h][m] ----------------
    float* stg = (float*)(smem + OFF_STG);
    float* outb = out + (size_t)b * HDIM * NDIM;
    const int rr = lid >> 2, qq = lid & 3;

    for (int hc2 = 0; hc2 < 8; hc2++) {
        const int p = hc2 & 1;
        CP_WAIT(0);                      // chunk hc2 resident
        __syncthreads();
        if (hc2 < 7) { issue_w(hc2 + 1, p ^ 1); CP_COMMIT(); }

        float cacc[8][4];
#pragma unroll
        for (int t = 0; t < 8; t++)
#pragma unroll
            for (int j = 0; j < 4; j++) cacc[t][j] = 0.f;

        const uint32_t whi = sbase + OFF_WB + p * WB_SZ;
        const uint32_t wlo = whi + 17408;
#pragma unroll
        for (int kk = 0; kk < 8; kk++) {
#pragma unroll
            for (int tp = 0; tp < 4; tp++) {
                uint32_t boff = b_off_w + (uint32_t)(tp * 16 * PADW + kk * 16) * 2;
                uint32_t bh[4], bl[4];
                ldsm4(bh, whi + boff);
                ldsm4(bl, wlo + boff);
                mma16816(cacc[2 * tp],     eh[kk], bh[0], bh[1]);
                mma16816(cacc[2 * tp],     eh[kk], bl[0], bl[1]);
                mma16816(cacc[2 * tp],     el[kk], bh[0], bh[1]);
                mma16816(cacc[2 * tp + 1], eh[kk], bh[2], bh[3]);
                mma16816(cacc[2 * tp + 1], eh[kk], bl[2], bl[3]);
                mma16816(cacc[2 * tp + 1], el[kk], bh[2], bh[3]);
            }
        }

        // scale by 1/sum and stage transposed: stg[h_local][n]
#pragma unroll
        for (int t = 0; t < 8; t++) {
            int hcl = t * 8 + 2 * qq;
            int n   = wid * 16 + rr;
            stg[(size_t)hcl * STGS + n]           = cacc[t][0] * r0;
            stg[(size_t)(hcl + 1) * STGS + n]     = cacc[t][1] * r0;
            stg[(size_t)hcl * STGS + n + 8]       = cacc[t][2] * r1;
            stg[(size_t)(hcl + 1) * STGS + n + 8] = cacc[t][3] * r1;
        }
        __syncthreads();

        // coalesced fp32 store: out[b][hc2*64+hr][n0 + ...]
#pragma unroll
        for (int it = 0; it < 8; it++) {
            int f = it * 128 + tid, hr = f >> 4, n4 = (f & 15) << 2;
            float4 v = *(const float4*)(stg + (size_t)hr * STGS + n4);
            *(float4*)(outb + (size_t)(hc2 * 64 + hr) * NDIM + n0 + n4) = v;
        }
        __syncthreads();                 // STG + WB[p] free for reuse
    }
}

// ============================================================
extern "C" void kernel_launch(void* const* d_in, const int* in_sizes, int n_in,
                              void* d_out, int out_size) {
    const float* H      = (const float*)d_in[0];  // [32,512,64,64]
    const float* W      = (const float*)d_in[1];  // [32,256,128]
    const float* head_w = (const float*)d_in[2];  // [512,256]
    float* out = (float*)d_out;

    cudaFuncSetAttribute(attn_kernel,
                         cudaFuncAttributeMaxDynamicSharedMemorySize, SMEM_DYN);

    proj_kernel<<<dim3(4, B_DIM), 256>>>(W, head_w);
    attn_kernel<<<dim3(NDIM / 64, B_DIM), 128, SMEM_DYN>>>(H, out);
}